// round 13
// baseline (speedup 1.0000x reference)
#include <cuda_runtime.h>
#include <stdint.h>
#include <math.h>

#define Bb 512
#define Nn 16
#define Cc 256
#define Kk 8192
#define MAXC 512

// ---------------- device globals (no allocations allowed) ----------------
__device__ float g_frest[Bb*Nn*Cc];
__device__ float g_fhat [Bb*Nn*Cc];
__device__ float g_rest [Bb*Nn*Cc];
__device__ __align__(256) signed char g_rest_q[Bb*Nn*Cc];
__device__ __align__(256) signed char g_emb_q[Kk*Cc];
__device__ float g_sa  [Bb*Nn];
__device__ float g_sb  [Kk];
__device__ float g_rsq  [Bb*Nn];
__device__ float g_esq  [Kk];
__device__ unsigned int g_dmin[Bb*Nn];          // fkey32 of min d-tilde
__device__ int g_ccnt[Bb*Nn];
__device__ int g_cand[Bb*Nn*MAXC];
__device__ unsigned long long g_win[Bb*Nn];
__device__ double g_loss;

// ---------------- helpers ----------------
__device__ __forceinline__ unsigned int smem_u32(const void* p){
    unsigned int a;
    asm("{ .reg .u64 t; cvta.to.shared.u64 t, %1; cvt.u32.u64 %0, t; }" : "=r"(a) : "l"(p));
    return a;
}
#define CP_ASYNC16(dst,src) asm volatile("cp.async.cg.shared.global [%0], [%1], 16;" :: "r"(dst), "l"(src))
#define CP_COMMIT()  asm volatile("cp.async.commit_group;" ::: "memory")
#define CP_WAIT1()   asm volatile("cp.async.wait_group 1;" ::: "memory")
#define CP_WAIT0()   asm volatile("cp.async.wait_group 0;" ::: "memory")

__device__ __forceinline__ void ldsm4(unsigned int* r, unsigned int addr){
    asm volatile("ldmatrix.sync.aligned.m8n8.x4.shared.b16 {%0,%1,%2,%3}, [%4];"
        : "=r"(r[0]),"=r"(r[1]),"=r"(r[2]),"=r"(r[3]) : "r"(addr));
}
__device__ __forceinline__ void mma_s8(int* d, const unsigned int* a, unsigned int b0, unsigned int b1){
    asm volatile("mma.sync.aligned.m16n8k32.row.col.s32.s8.s8.s32 "
        "{%0,%1,%2,%3}, {%4,%5,%6,%7}, {%8,%9}, {%0,%1,%2,%3};"
        : "+r"(d[0]),"+r"(d[1]),"+r"(d[2]),"+r"(d[3])
        : "r"(a[0]),"r"(a[1]),"r"(a[2]),"r"(a[3]), "r"(b0),"r"(b1));
}
__device__ __forceinline__ unsigned int fkey(float f){
    unsigned int u = __float_as_uint(f);
    return (u & 0x80000000u) ? ~u : (u | 0x80000000u);
}
__device__ __forceinline__ float unfkey(unsigned int k){
    unsigned int u = (k & 0x80000000u) ? (k & 0x7FFFFFFFu) : ~k;
    return __uint_as_float(u);
}

// ---------------- prep / pool / update kernels ----------------
__global__ void init_kernel(const float* __restrict__ f){
    int i = blockIdx.x*blockDim.x + threadIdx.x;
    if (i < Bb*Nn*Cc){ g_frest[i] = f[i]; g_fhat[i] = 0.0f; }
    if (i == 0) g_loss = 0.0;
}

// per code k: esq (sequential FMA, unchanged — feeds exact path) + int8 quantization
__global__ void prep_emb_kernel(const float* __restrict__ emb){
    int k = blockIdx.x*blockDim.x + threadIdx.x;
    if (k >= Kk) return;
    const float* e = emb + (size_t)k*Cc;
    float acc = 0.0f, amax = 0.0f;
    #pragma unroll 4
    for (int c=0;c<Cc;c++){
        float v = e[c];
        acc = fmaf(v, v, acc);
        amax = fmaxf(amax, fabsf(v));
    }
    float sb = fmaxf(amax, 1e-20f) * (1.0f/127.0f);
    #pragma unroll 4
    for (int c=0;c<Cc;c++)
        g_emb_q[(size_t)k*Cc + c] = (signed char)(int)rintf(e[c]/sb);
    g_esq[k] = acc;
    g_sb[k] = sb;
}

// pool over n; emit fp32 rest + int8 quant; rsq (sequential order); init per-row state
__global__ void pool_rsq_kernel(int pn){
    __shared__ float sr[256];
    __shared__ float s_sa;
    int row = blockIdx.x;          // 0..B*pn-1
    int c   = threadIdx.x;
    int b = row / pn, p = row % pn;
    int s = (p*Nn)/pn;
    int e = ((p+1)*Nn + pn - 1)/pn;
    float w = (float)(1.0/(double)(e-s));
    float acc = 0.0f;
    for (int n=s;n<e;n++) acc = fmaf(w, g_frest[((size_t)b*Nn+n)*Cc + c], acc);
    size_t o = (size_t)row*Cc + c;
    g_rest[o] = acc;
    sr[c] = acc;
    __syncthreads();
    if (c == 0){
        float r = 0.0f, amax = 0.0f;
        #pragma unroll 8
        for (int i=0;i<Cc;i++){ r = fmaf(sr[i], sr[i], r); amax = fmaxf(amax, fabsf(sr[i])); }
        g_rsq[row] = r;
        float sa = fmaxf(amax, 1e-20f) * (1.0f/127.0f);
        g_sa[row] = sa;
        s_sa = sa;
        g_dmin[row] = 0xFFFFFFFFu;
        g_ccnt[row] = 0;
        g_win[row] = 0xFFFFFFFFFFFFFFFFull;
    }
    __syncthreads();
    g_rest_q[o] = (signed char)(int)rintf(acc / s_sa);
}

// ---------------- phase 1: int8 GEMM filter ----------------
// CTA: 512 thr (16 warps, 4x4), tile 128(rows) x 128(codes), K-chunks of 64 dims (64B).
// Warp tile 32x32, mma m16n8k32 s8. 3-stage cp.async ring, one sync per chunk.
// Row stride 80B (64B data + 16B pad) -> conflict-free ldmatrix.
#define KC 64
#define ROWB 80
#define REG_STRIDE (128*ROWB)          // 10240
#define STAGE_BYTES (2*REG_STRIDE)     // 20480 (A region + B region)
#define NSTAGE 3
#define SMEM_GEMM (NSTAGE*STAGE_BYTES) // 61440

__global__ __launch_bounds__(512,2) void gemm_filter_kernel(){
    extern __shared__ char smem[];
    __shared__ unsigned int sdmin[128];
    __shared__ float sthr[128];
    const int tid = threadIdx.x, lane = tid & 31, wid = tid >> 5;
    const int wm = wid >> 2, wn = wid & 3;     // 4 x 32 rows, 4 x 32 cols
    const int row0 = blockIdx.y * 128, k0 = blockIdx.x * 128;
    const unsigned int sbase = smem_u32(smem);

    if (tid < 128) sdmin[tid] = 0xFFFFFFFFu;

    int acc[2][4][4];
    #pragma unroll
    for (int i=0;i<2;i++)
        #pragma unroll
        for (int j=0;j<4;j++)
            #pragma unroll
            for (int q=0;q<4;q++) acc[i][j][q] = 0;

    // cp.async: per stage, A region 128 rows x 64B = 512 x 16B; 512 threads -> 1 each. Same for B.
    const int arow = tid >> 2, apos = (tid & 3);
    const char* srcA = (const char*)(g_rest_q + (size_t)(row0+arow)*Cc) + apos*16;
    const char* srcB = (const char*)(g_emb_q  + (size_t)(k0 +arow)*Cc) + apos*16;
    const unsigned int adst = arow*ROWB + apos*16;

    // prologue: chunks 0 and 1 -> stages 0 and 1
    #pragma unroll
    for (int c=0;c<2;c++){
        unsigned int st = sbase + c*STAGE_BYTES;
        CP_ASYNC16(st + adst,              srcA + c*KC);
        CP_ASYNC16(st + adst + REG_STRIDE, srcB + c*KC);
        CP_COMMIT();
    }

    const int NCHUNK = Cc / KC;   // 4
    int stage = 0;
    for (int c = 0; c < NCHUNK; c++){
        if (c + 1 < NCHUNK) CP_WAIT1(); else CP_WAIT0();
        __syncthreads();   // chunk c visible; all warps done with stage of chunk c-1

        if (c + 2 < NCHUNK){
            int ns = stage + 2; if (ns >= NSTAGE) ns -= NSTAGE;
            unsigned int st = sbase + ns*STAGE_BYTES;
            CP_ASYNC16(st + adst,              srcA + (c+2)*KC);
            CP_ASYNC16(st + adst + REG_STRIDE, srcB + (c+2)*KC);
            CP_COMMIT();
        }

        unsigned int aA = sbase + stage*STAGE_BYTES;
        unsigned int aB = aA + REG_STRIDE;

        #pragma unroll
        for (int ks=0; ks<2; ks++){           // 2 x 32-dim (32B) k-steps per chunk
            unsigned int offA = (unsigned int)((wm*32 + (lane&15))*ROWB + ks*32 + ((lane>>4)<<4));
            unsigned int offB = (unsigned int)((wn*32 + (lane&15))*ROWB + ks*32 + ((lane>>4)<<4));
            // B: 2 x ldsm4, each covers 16 codes x 32B
            unsigned int bq[2][4];
            ldsm4(bq[0], aB + offB);
            ldsm4(bq[1], aB + offB + 16*ROWB);
            // A: 2 x ldsm4, each covers 16 rows x 32B
            unsigned int ah[2][4];
            #pragma unroll
            for (int i=0;i<2;i++) ldsm4(ah[i], aA + offA + i*16*ROWB);
            #pragma unroll
            for (int i=0;i<2;i++)
                #pragma unroll
                for (int q=0;q<2;q++)
                    #pragma unroll
                    for (int p=0;p<2;p++)
                        mma_s8(acc[i][2*q+p], ah[i], bq[q][p], bq[q][p+2]);
        }
        stage++; if (stage >= NSTAGE) stage -= NSTAGE;
    }

    // ---- epilogue pass 1: tile min of d-tilde per row ----
    const int lr = lane >> 2, lc2 = (lane & 3)*2;
    float rsqv[2][2], sav[2][2], esv[4][2], sbv[4][2];
    #pragma unroll
    for (int i=0;i<2;i++){
        int rl = row0 + wm*32 + i*16 + lr;
        rsqv[i][0] = g_rsq[rl];     rsqv[i][1] = g_rsq[rl + 8];
        sav[i][0]  = -2.0f*g_sa[rl]; sav[i][1] = -2.0f*g_sa[rl + 8];
    }
    #pragma unroll
    for (int j=0;j<4;j++){
        int cl = k0 + wn*32 + j*8 + lc2;
        esv[j][0] = g_esq[cl]; esv[j][1] = g_esq[cl+1];
        sbv[j][0] = g_sb[cl];  sbv[j][1] = g_sb[cl+1];
    }
    #pragma unroll
    for (int i=0;i<2;i++){
        unsigned int klo = 0xFFFFFFFFu, khi = 0xFFFFFFFFu;
        #pragma unroll
        for (int j=0;j<4;j++){
            float f00 = __int2float_rn(acc[i][j][0]);
            float f01 = __int2float_rn(acc[i][j][1]);
            float f10 = __int2float_rn(acc[i][j][2]);
            float f11 = __int2float_rn(acc[i][j][3]);
            unsigned int k00 = fkey(fmaf(sav[i][0]*sbv[j][0], f00, rsqv[i][0] + esv[j][0]));
            unsigned int k01 = fkey(fmaf(sav[i][0]*sbv[j][1], f01, rsqv[i][0] + esv[j][1]));
            unsigned int k10 = fkey(fmaf(sav[i][1]*sbv[j][0], f10, rsqv[i][1] + esv[j][0]));
            unsigned int k11 = fkey(fmaf(sav[i][1]*sbv[j][1], f11, rsqv[i][1] + esv[j][1]));
            klo = min(klo, min(k00,k01));
            khi = min(khi, min(k10,k11));
        }
        #pragma unroll
        for (int off=1; off<=2; off<<=1){
            klo = min(klo, __shfl_xor_sync(0xffffffffu, klo, off));
            khi = min(khi, __shfl_xor_sync(0xffffffffu, khi, off));
        }
        if ((lane & 3) == 0){
            atomicMin(&sdmin[wm*32 + i*16 + lr],     klo);
            atomicMin(&sdmin[wm*32 + i*16 + lr + 8], khi);
        }
    }
    __syncthreads();

    // ---- global min + threshold ----
    if (tid < 128){
        unsigned int old = atomicMin(&g_dmin[row0 + tid], sdmin[tid]);
        unsigned int m = min(old, sdmin[tid]);
        float dm = unfkey(m);
        float rsq = g_rsq[row0 + tid];
        sthr[tid] = dm + (rsq*3e-7f + 2e-4f);
    }
    __syncthreads();

    // ---- epilogue pass 2: append candidates below threshold ----
    #pragma unroll
    for (int i=0;i<2;i++){
        int rlo = wm*32 + i*16 + lr;
        int rhi = rlo + 8;
        float tlo = sthr[rlo], thi = sthr[rhi];
        #pragma unroll
        for (int j=0;j<4;j++){
            int col = k0 + wn*32 + j*8 + lc2;
            float f00 = __int2float_rn(acc[i][j][0]);
            float f01 = __int2float_rn(acc[i][j][1]);
            float f10 = __int2float_rn(acc[i][j][2]);
            float f11 = __int2float_rn(acc[i][j][3]);
            float d00 = fmaf(sav[i][0]*sbv[j][0], f00, rsqv[i][0] + esv[j][0]);
            float d01 = fmaf(sav[i][0]*sbv[j][1], f01, rsqv[i][0] + esv[j][1]);
            float d10 = fmaf(sav[i][1]*sbv[j][0], f10, rsqv[i][1] + esv[j][0]);
            float d11 = fmaf(sav[i][1]*sbv[j][1], f11, rsqv[i][1] + esv[j][1]);
            if (d00 < tlo){ int s = atomicAdd(&g_ccnt[row0+rlo], 1); if (s < MAXC) g_cand[(size_t)(row0+rlo)*MAXC + s] = col; }
            if (d01 < tlo){ int s = atomicAdd(&g_ccnt[row0+rlo], 1); if (s < MAXC) g_cand[(size_t)(row0+rlo)*MAXC + s] = col+1; }
            if (d10 < thi){ int s = atomicAdd(&g_ccnt[row0+rhi], 1); if (s < MAXC) g_cand[(size_t)(row0+rhi)*MAXC + s] = col; }
            if (d11 < thi){ int s = atomicAdd(&g_ccnt[row0+rhi], 1); if (s < MAXC) g_cand[(size_t)(row0+rhi)*MAXC + s] = col+1; }
        }
    }
}

// ---------------- phase 2: exact rescore of candidates ----------------
__global__ void rescore_kernel(const float* __restrict__ emb){
    __shared__ float srest[256];
    int row = blockIdx.x;
    int tid = threadIdx.x;
    srest[tid]       = g_rest[(size_t)row*Cc + tid];
    srest[tid + 128] = g_rest[(size_t)row*Cc + tid + 128];
    __syncthreads();
    int cnt = g_ccnt[row];
    if (cnt > MAXC) cnt = MAXC;
    float rsq = g_rsq[row];
    for (int t = tid; t < cnt; t += 128){
        int k = g_cand[(size_t)row*MAXC + t];
        const float* e = emb + (size_t)k*Cc;
        float acc = 0.0f;
        #pragma unroll 8
        for (int c=0;c<Cc;c++) acc = fmaf(srest[c], __ldg(e + c), acc);
        float d = fmaf(-2.0f, acc, rsq + g_esq[k]);
        unsigned long long key = ((unsigned long long)fkey(d) << 32) | (unsigned int)k;
        atomicMin(&g_win[row], key);
    }
}

// ---------------- winner gather / residual update / loss ----------------
__global__ void update_kernel(const float* __restrict__ f, const float* __restrict__ emb, int pn){
    __shared__ double sred[256];
    int bn = blockIdx.x;
    int b = bn >> 4, n = bn & 15;
    int c = threadIdx.x;

    float h;
    if (pn == Nn){
        int k0 = (int)(g_win[(size_t)b*pn + n] & 0xFFFFFFFFull);
        h = emb[(size_t)k0*Cc + c];
    } else {
        double scale = (double)pn / 16.0;
        double pos = ((double)n + 0.5)*scale - 0.5;
        if (pos < 0.0) pos = 0.0;
        int i0 = (int)floor(pos);
        if (i0 > pn-1) i0 = pn-1;
        double frac = pos - (double)i0;
        int i1 = i0 + 1; if (i1 > pn-1) i1 = pn-1;
        float w0 = (float)(1.0 - frac);
        int k0 = (int)(g_win[(size_t)b*pn + i0] & 0xFFFFFFFFull);
        if (i1 == i0){
            float w = (float)((double)w0 + frac);
            h = w * emb[(size_t)k0*Cc + c];
        } else {
            float w1 = (float)frac;
            int k1 = (int)(g_win[(size_t)b*pn + i1] & 0xFFFFFFFFull);
            h = fmaf(w1, emb[(size_t)k1*Cc + c], w0 * emb[(size_t)k0*Cc + c]);
        }
    }

    size_t idx = (size_t)bn*Cc + c;
    float fh = g_fhat[idx] + h;
    g_fhat[idx] = fh;
    g_frest[idx] = g_frest[idx] - h;
    float t = fh - f[idx];
    sred[c] = (double)t * (double)t;
    __syncthreads();
    for (int s=128;s>0;s>>=1){
        if (c < s) sred[c] += sred[c+s];
        __syncthreads();
    }
    if (c == 0) atomicAdd(&g_loss, sred[0]);
}

__global__ void finalize_kernel(float* __restrict__ out){
    int i = blockIdx.x*blockDim.x + threadIdx.x;
    if (i < Bb*Nn*Cc) out[i] = g_fhat[i];
    if (i == 0){
        double S = g_loss / (double)(Bb*Nn*Cc);
        out[Bb*Nn*Cc]     = (float)(0.25 * S / 16.0);   // commit
        out[Bb*Nn*Cc + 1] = (float)(S / 16.0);          // qlat
    }
}

extern "C" void kernel_launch(void* const* d_in, const int* in_sizes, int n_in,
                              void* d_out, int out_size){
    const float* f   = (const float*)d_in[0];
    const float* emb = (const float*)d_in[1];
    float* out = (float*)d_out;

    cudaFuncSetAttribute(gemm_filter_kernel, cudaFuncAttributeMaxDynamicSharedMemorySize, SMEM_GEMM);

    init_kernel<<<(Bb*Nn*Cc + 255)/256, 256>>>(f);
    prep_emb_kernel<<<(Kk + 255)/256, 256>>>(emb);

    for (int pn=1; pn<=Nn; pn++){
        int M = Bb*pn;
        pool_rsq_kernel<<<M, 256>>>(pn);
        dim3 grid(Kk/128, M/128);
        gemm_filter_kernel<<<grid, 512, SMEM_GEMM>>>();
        rescore_kernel<<<M, 128>>>(emb);
        update_kernel<<<Bb*Nn, 256>>>(f, emb, pn);
    }
    finalize_kernel<<<(Bb*Nn*Cc + 255)/256, 256>>>(out);
}

// round 14
// speedup vs baseline: 1.4404x; 1.4404x over previous
#include <cuda_runtime.h>
#include <cuda_bf16.h>
#include <stdint.h>
#include <math.h>

#define Bb 512
#define Nn 16
#define Cc 256
#define Kk 8192
#define MAXC 512

// ---------------- device globals (no allocations allowed) ----------------
__device__ float g_frest[Bb*Nn*Cc];
__device__ float g_fhat [Bb*Nn*Cc];
__device__ float g_rest [Bb*Nn*Cc];
__device__ __nv_bfloat16 g_rest_h[Bb*Nn*Cc];
__device__ __nv_bfloat16 g_emb_h[Kk*Cc];
__device__ float g_rsq  [Bb*Nn];
__device__ float g_esq  [Kk];
__device__ unsigned int g_dmin[Bb*Nn];          // fkey32 of min d-tilde
__device__ int g_ccnt[Bb*Nn];
__device__ int g_cand[Bb*Nn*MAXC];
__device__ double g_loss;

// ---------------- helpers ----------------
__device__ __forceinline__ unsigned int smem_u32(const void* p){
    unsigned int a;
    asm("{ .reg .u64 t; cvta.to.shared.u64 t, %1; cvt.u32.u64 %0, t; }" : "=r"(a) : "l"(p));
    return a;
}
#define CP_ASYNC16(dst,src) asm volatile("cp.async.cg.shared.global [%0], [%1], 16;" :: "r"(dst), "l"(src))
#define CP_COMMIT()  asm volatile("cp.async.commit_group;" ::: "memory")
#define CP_WAIT1()   asm volatile("cp.async.wait_group 1;" ::: "memory")
#define CP_WAIT0()   asm volatile("cp.async.wait_group 0;" ::: "memory")

__device__ __forceinline__ void ldsm4(unsigned int* r, unsigned int addr){
    asm volatile("ldmatrix.sync.aligned.m8n8.x4.shared.b16 {%0,%1,%2,%3}, [%4];"
        : "=r"(r[0]),"=r"(r[1]),"=r"(r[2]),"=r"(r[3]) : "r"(addr));
}
__device__ __forceinline__ void mma_bf16(float* d, const unsigned int* a, const unsigned int* b){
    asm volatile("mma.sync.aligned.m16n8k16.row.col.f32.bf16.bf16.f32 "
        "{%0,%1,%2,%3}, {%4,%5,%6,%7}, {%8,%9}, {%0,%1,%2,%3};"
        : "+f"(d[0]),"+f"(d[1]),"+f"(d[2]),"+f"(d[3])
        : "r"(a[0]),"r"(a[1]),"r"(a[2]),"r"(a[3]), "r"(b[0]),"r"(b[1]));
}
__device__ __forceinline__ unsigned int fkey(float f){
    unsigned int u = __float_as_uint(f);
    return (u & 0x80000000u) ? ~u : (u | 0x80000000u);
}
__device__ __forceinline__ float unfkey(unsigned int k){
    unsigned int u = (k & 0x80000000u) ? (k & 0x7FFFFFFFu) : ~k;
    return __uint_as_float(u);
}

// ---------------- prep ----------------
__global__ void prep_emb_kernel(const float* __restrict__ emb){
    int k = blockIdx.x*blockDim.x + threadIdx.x;
    if (k >= Kk) return;
    const float* e = emb + (size_t)k*Cc;
    float acc = 0.0f;
    #pragma unroll 4
    for (int c=0;c<Cc;c++){
        float v = e[c];
        acc = fmaf(v, v, acc);
        g_emb_h[(size_t)k*Cc + c] = __float2bfloat16_rn(v);
    }
    g_esq[k] = acc;
}

// one block per b: frest=f, fhat=0, pool for pn=1, rsq, per-row state init
__global__ void init_pool_kernel(const float* __restrict__ f){
    __shared__ float s_pool[256];
    int b = blockIdx.x, c = threadIdx.x;
    float acc = 0.0f;
    const float w = (float)(1.0/16.0);
    for (int n=0;n<Nn;n++){
        size_t gi = ((size_t)b*Nn+n)*Cc + c;
        float v = f[gi];
        g_frest[gi] = v;
        g_fhat[gi] = 0.0f;
        acc = fmaf(w, v, acc);
    }
    size_t o = (size_t)b*Cc + c;
    g_rest[o] = acc;
    g_rest_h[o] = __float2bfloat16_rn(acc);
    s_pool[c] = acc;
    __syncthreads();
    if (c == 0){
        float r = 0.0f;
        #pragma unroll 8
        for (int i=0;i<Cc;i++) r = fmaf(s_pool[i], s_pool[i], r);
        g_rsq[b] = r;
        g_dmin[b] = 0xFFFFFFFFu;
        g_ccnt[b] = 0;
        if (b == 0) g_loss = 0.0;
    }
}

// ---------------- phase 1: bf16 hi-limb GEMM filter ----------------
// CTA: 512 thr (16 warps, 4x4), tile 128(rows) x 128(codes), K-chunks of 64.
// Warp tile 32x32. 3-stage cp.async ring, one __syncthreads per chunk (4 chunks).
// Row stride 144B (128B data + 16B pad); gcd(9,8)=1 -> conflict-free ldmatrix.
#define KC 64
#define ROWB 144
#define REG_STRIDE (128*ROWB)          // 18432
#define STAGE_BYTES (2*REG_STRIDE)     // 36864
#define NSTAGE 3
#define SMEM_GEMM (NSTAGE*STAGE_BYTES) // 110592

__global__ __launch_bounds__(512,2) void gemm_filter_kernel(){
    extern __shared__ char smem[];
    __shared__ unsigned int sdmin[128];
    __shared__ float sthr[128];
    const int tid = threadIdx.x, lane = tid & 31, wid = tid >> 5;
    const int wm = wid >> 2, wn = wid & 3;
    const int row0 = blockIdx.y * 128, k0 = blockIdx.x * 128;
    const unsigned int sbase = smem_u32(smem);

    if (tid < 128) sdmin[tid] = 0xFFFFFFFFu;

    float acc[2][4][4];
    #pragma unroll
    for (int i=0;i<2;i++)
        #pragma unroll
        for (int j=0;j<4;j++)
            #pragma unroll
            for (int q=0;q<4;q++) acc[i][j][q] = 0.0f;

    const int arow = tid >> 2, apos = (tid & 3) * 2;
    const char* srcA = (const char*)(g_rest_h + (size_t)(row0+arow)*Cc) + apos*16;
    const char* srcB = (const char*)(g_emb_h  + (size_t)(k0 +arow)*Cc) + apos*16;
    const unsigned int adst = arow*ROWB + apos*16;

    #pragma unroll
    for (int c=0;c<2;c++){
        unsigned int st = sbase + c*STAGE_BYTES;
        CP_ASYNC16(st + adst,                   srcA + c*(KC*2));
        CP_ASYNC16(st + adst + 16,              srcA + c*(KC*2) + 16);
        CP_ASYNC16(st + adst + REG_STRIDE,      srcB + c*(KC*2));
        CP_ASYNC16(st + adst + REG_STRIDE + 16, srcB + c*(KC*2) + 16);
        CP_COMMIT();
    }

    const int NCHUNK = Cc / KC;   // 4
    int stage = 0;
    for (int c = 0; c < NCHUNK; c++){
        if (c + 1 < NCHUNK) CP_WAIT1(); else CP_WAIT0();
        __syncthreads();

        if (c + 2 < NCHUNK){
            int ns = stage + 2; if (ns >= NSTAGE) ns -= NSTAGE;
            unsigned int st = sbase + ns*STAGE_BYTES;
            CP_ASYNC16(st + adst,                   srcA + (c+2)*(KC*2));
            CP_ASYNC16(st + adst + 16,              srcA + (c+2)*(KC*2) + 16);
            CP_ASYNC16(st + adst + REG_STRIDE,      srcB + (c+2)*(KC*2));
            CP_ASYNC16(st + adst + REG_STRIDE + 16, srcB + (c+2)*(KC*2) + 16);
            CP_COMMIT();
        }

        unsigned int aA = sbase + stage*STAGE_BYTES;
        unsigned int aB = aA + REG_STRIDE;

        #pragma unroll
        for (int ks=0; ks<4; ks++){
            unsigned int offA = (unsigned int)((wm*32 + (lane&15))*ROWB + (ks*16 + ((lane>>4)<<3))*2);
            unsigned int offB = (unsigned int)((wn*32 + (lane&7) + ((lane>>4)<<3))*ROWB
                                             + (ks*16 + (((lane>>3)&1)<<3))*2);
            unsigned int bh[8];
            ldsm4(bh+0, aB + offB); ldsm4(bh+4, aB + offB + 16*ROWB);
            unsigned int ah[2][4];
            #pragma unroll
            for (int i=0;i<2;i++) ldsm4(ah[i], aA + offA + i*16*ROWB);
            #pragma unroll
            for (int i=0;i<2;i++)
                #pragma unroll
                for (int j=0;j<4;j++)
                    mma_bf16(acc[i][j], ah[i], bh + 2*j);
        }
        stage++; if (stage >= NSTAGE) stage -= NSTAGE;
    }

    // ---- epilogue pass 1: tile min of d-tilde per row ----
    const int lr = lane >> 2, lc2 = (lane & 3)*2;
    float rsqv[2][2], esv[4][2];
    #pragma unroll
    for (int i=0;i<2;i++){
        rsqv[i][0] = g_rsq[row0 + wm*32 + i*16 + lr];
        rsqv[i][1] = g_rsq[row0 + wm*32 + i*16 + lr + 8];
    }
    #pragma unroll
    for (int j=0;j<4;j++){
        esv[j][0] = g_esq[k0 + wn*32 + j*8 + lc2];
        esv[j][1] = g_esq[k0 + wn*32 + j*8 + lc2 + 1];
    }
    #pragma unroll
    for (int i=0;i<2;i++){
        unsigned int klo = 0xFFFFFFFFu, khi = 0xFFFFFFFFu;
        #pragma unroll
        for (int j=0;j<4;j++){
            unsigned int k00 = fkey(fmaf(-2.0f, acc[i][j][0], rsqv[i][0] + esv[j][0]));
            unsigned int k01 = fkey(fmaf(-2.0f, acc[i][j][1], rsqv[i][0] + esv[j][1]));
            unsigned int k10 = fkey(fmaf(-2.0f, acc[i][j][2], rsqv[i][1] + esv[j][0]));
            unsigned int k11 = fkey(fmaf(-2.0f, acc[i][j][3], rsqv[i][1] + esv[j][1]));
            klo = min(klo, min(k00,k01));
            khi = min(khi, min(k10,k11));
        }
        #pragma unroll
        for (int off=1; off<=2; off<<=1){
            klo = min(klo, __shfl_xor_sync(0xffffffffu, klo, off));
            khi = min(khi, __shfl_xor_sync(0xffffffffu, khi, off));
        }
        if ((lane & 3) == 0){
            atomicMin(&sdmin[wm*32 + i*16 + lr],     klo);
            atomicMin(&sdmin[wm*32 + i*16 + lr + 8], khi);
        }
    }
    __syncthreads();

    if (tid < 128){
        unsigned int old = atomicMin(&g_dmin[row0 + tid], sdmin[tid]);
        unsigned int m = min(old, sdmin[tid]);
        float dm = unfkey(m);
        float rsq = g_rsq[row0 + tid];
        sthr[tid] = dm + (rsq*4e-7f + 8e-5f);
    }
    __syncthreads();

    // ---- epilogue pass 2: append candidates below threshold ----
    #pragma unroll
    for (int i=0;i<2;i++){
        int rlo = wm*32 + i*16 + lr;
        int rhi = rlo + 8;
        float tlo = sthr[rlo], thi = sthr[rhi];
        #pragma unroll
        for (int j=0;j<4;j++){
            int col = k0 + wn*32 + j*8 + lc2;
            float d00 = fmaf(-2.0f, acc[i][j][0], rsqv[i][0] + esv[j][0]);
            float d01 = fmaf(-2.0f, acc[i][j][1], rsqv[i][0] + esv[j][1]);
            float d10 = fmaf(-2.0f, acc[i][j][2], rsqv[i][1] + esv[j][0]);
            float d11 = fmaf(-2.0f, acc[i][j][3], rsqv[i][1] + esv[j][1]);
            if (d00 < tlo){ int s = atomicAdd(&g_ccnt[row0+rlo], 1); if (s < MAXC) g_cand[(size_t)(row0+rlo)*MAXC + s] = col; }
            if (d01 < tlo){ int s = atomicAdd(&g_ccnt[row0+rlo], 1); if (s < MAXC) g_cand[(size_t)(row0+rlo)*MAXC + s] = col+1; }
            if (d10 < thi){ int s = atomicAdd(&g_ccnt[row0+rhi], 1); if (s < MAXC) g_cand[(size_t)(row0+rhi)*MAXC + s] = col; }
            if (d11 < thi){ int s = atomicAdd(&g_ccnt[row0+rhi], 1); if (s < MAXC) g_cand[(size_t)(row0+rhi)*MAXC + s] = col+1; }
        }
    }
}

// ---------------- fused: rescore + update + pool(next) ----------------
// One block per b (256 threads). Dyn smem: s_rest[pn*256] | s_frest[16*256] | s_pool[(pn+1)*256]
#define SMEM_FUSE (3*16*256*4)

__global__ __launch_bounds__(256) void fuse_kernel(const float* __restrict__ f,
                                                  const float* __restrict__ emb, int pn){
    extern __shared__ float sm[];
    float* s_rest  = sm;
    float* s_frest = sm + pn*Cc;
    float* s_pool  = s_frest + Nn*Cc;
    __shared__ unsigned long long s_win[16];
    __shared__ int s_off[17];
    __shared__ double s_red[256];
    const int b = blockIdx.x, tid = threadIdx.x;
    const int base_row = b*pn;

    for (int i=tid; i<pn*Cc; i+=256) s_rest[i]  = g_rest[(size_t)base_row*Cc + i];
    for (int i=tid; i<Nn*Cc; i+=256) s_frest[i] = g_frest[((size_t)b*Nn)*Cc + i];
    if (tid < pn){
        int cnt = g_ccnt[base_row+tid]; if (cnt > MAXC) cnt = MAXC;
        s_off[tid+1] = cnt;
        s_win[tid] = 0xFFFFFFFFFFFFFFFFull;
    }
    __syncthreads();
    if (tid == 0){ s_off[0] = 0; for (int p=0;p<pn;p++) s_off[p+1] += s_off[p]; }
    __syncthreads();

    // exact rescore: one thread per candidate, sequential fp32 FMA dot
    int T = s_off[pn];
    for (int g=tid; g<T; g+=256){
        int p = 0;
        while (s_off[p+1] <= g) p++;
        int k = g_cand[(size_t)(base_row+p)*MAXC + (g - s_off[p])];
        const float* e = emb + (size_t)k*Cc;
        const float* r = s_rest + p*Cc;
        float acc = 0.0f;
        #pragma unroll 8
        for (int c=0;c<Cc;c++) acc = fmaf(r[c], __ldg(e+c), acc);
        float d = fmaf(-2.0f, acc, g_rsq[base_row+p] + g_esq[k]);
        unsigned long long key = ((unsigned long long)fkey(d) << 32) | (unsigned int)k;
        atomicMin(&s_win[p], key);
    }
    __syncthreads();

    // update f_hat / f_rest + loss
    const int c = tid;
    double lloss = 0.0;
    for (int n=0;n<Nn;n++){
        float h;
        if (pn == Nn){
            int k0 = (int)(s_win[n] & 0xFFFFFFFFull);
            h = emb[(size_t)k0*Cc + c];
        } else {
            double scale = (double)pn / 16.0;
            double pos = ((double)n + 0.5)*scale - 0.5;
            if (pos < 0.0) pos = 0.0;
            int i0 = (int)floor(pos);
            if (i0 > pn-1) i0 = pn-1;
            double frac = pos - (double)i0;
            int i1 = i0 + 1; if (i1 > pn-1) i1 = pn-1;
            float w0 = (float)(1.0 - frac);
            int k0 = (int)(s_win[i0] & 0xFFFFFFFFull);
            if (i1 == i0){
                float w = (float)((double)w0 + frac);
                h = w * emb[(size_t)k0*Cc + c];
            } else {
                float w1 = (float)frac;
                int k1 = (int)(s_win[i1] & 0xFFFFFFFFull);
                h = fmaf(w1, emb[(size_t)k1*Cc + c], w0 * emb[(size_t)k0*Cc + c]);
            }
        }
        size_t gi = ((size_t)b*Nn + n)*Cc + c;
        int si = n*Cc + c;
        float fh = g_fhat[gi] + h;
        g_fhat[gi] = fh;
        float fr = s_frest[si] - h;
        s_frest[si] = fr;
        g_frest[gi] = fr;
        float t = fh - f[gi];
        lloss += (double)t * (double)t;
    }
    s_red[tid] = lloss;
    __syncthreads();
    for (int s=128;s>0;s>>=1){
        if (tid < s) s_red[tid] += s_red[tid+s];
        __syncthreads();
    }
    if (tid == 0) atomicAdd(&g_loss, s_red[0]);

    // pool for next stage
    if (pn < Nn){
        int np = pn + 1;
        for (int p=0;p<np;p++){
            int s = (p*Nn)/np;
            int e2 = ((p+1)*Nn + np - 1)/np;
            float w = (float)(1.0/(double)(e2-s));
            float acc = 0.0f;
            for (int n=s;n<e2;n++) acc = fmaf(w, s_frest[n*Cc + c], acc);
            size_t o = ((size_t)(b*np + p))*Cc + c;
            g_rest[o] = acc;
            g_rest_h[o] = __float2bfloat16_rn(acc);
            s_pool[p*Cc + c] = acc;
        }
        __syncthreads();
        if (tid < np){
            const float* pr = s_pool + tid*Cc;
            float r = 0.0f;
            #pragma unroll 8
            for (int i=0;i<Cc;i++) r = fmaf(pr[i], pr[i], r);
            int row = b*np + tid;
            g_rsq[row] = r;
            g_dmin[row] = 0xFFFFFFFFu;
            g_ccnt[row] = 0;
        }
    }
}

__global__ void finalize_kernel(float* __restrict__ out){
    int i = blockIdx.x*blockDim.x + threadIdx.x;
    if (i < Bb*Nn*Cc) out[i] = g_fhat[i];
    if (i == 0){
        double S = g_loss / (double)(Bb*Nn*Cc);
        out[Bb*Nn*Cc]     = (float)(0.25 * S / 16.0);   // commit
        out[Bb*Nn*Cc + 1] = (float)(S / 16.0);          // qlat
    }
}

extern "C" void kernel_launch(void* const* d_in, const int* in_sizes, int n_in,
                              void* d_out, int out_size){
    const float* f   = (const float*)d_in[0];
    const float* emb = (const float*)d_in[1];
    float* out = (float*)d_out;

    cudaFuncSetAttribute(gemm_filter_kernel, cudaFuncAttributeMaxDynamicSharedMemorySize, SMEM_GEMM);
    cudaFuncSetAttribute(fuse_kernel, cudaFuncAttributeMaxDynamicSharedMemorySize, SMEM_FUSE);

    prep_emb_kernel<<<(Kk + 255)/256, 256>>>(emb);
    init_pool_kernel<<<Bb, 256>>>(f);

    for (int pn=1; pn<=Nn; pn++){
        int M = Bb*pn;
        dim3 grid(Kk/128, M/128);
        gemm_filter_kernel<<<grid, 512, SMEM_GEMM>>>();
        fuse_kernel<<<Bb, 256, SMEM_FUSE>>>(f, emb, pn);
    }
    finalize_kernel<<<(Bb*Nn*Cc + 255)/256, 256>>>(out);
}

// round 16
// speedup vs baseline: 1.8049x; 1.2530x over previous
#include <cuda_runtime.h>
#include <cuda_bf16.h>
#include <stdint.h>
#include <math.h>

#define Bb 512
#define Nn 16
#define Cc 256
#define Kk 8192
#define MAXC 512

// ---------------- device globals (no allocations allowed) ----------------
__device__ float g_frest[Bb*Nn*Cc];
__device__ float g_fhat [Bb*Nn*Cc];
__device__ __nv_bfloat16 g_rest_h[Bb*Nn*Cc];
__device__ __nv_bfloat16 g_emb_h[Kk*Cc];
__device__ float g_rsq  [Bb*Nn];
__device__ float g_esq  [Kk];
__device__ unsigned int g_dmin[Bb*Nn];
__device__ int g_ccnt[Bb*Nn];
__device__ int g_cand[Bb*Nn*MAXC];
__device__ double g_loss;

// ---------------- helpers ----------------
__device__ __forceinline__ unsigned int smem_u32(const void* p){
    unsigned int a;
    asm("{ .reg .u64 t; cvta.to.shared.u64 t, %1; cvt.u32.u64 %0, t; }" : "=r"(a) : "l"(p));
    return a;
}
#define CP_ASYNC16(dst,src) asm volatile("cp.async.cg.shared.global [%0], [%1], 16;" :: "r"(dst), "l"(src))
#define CP_COMMIT()  asm volatile("cp.async.commit_group;" ::: "memory")
#define CP_WAIT1()   asm volatile("cp.async.wait_group 1;" ::: "memory")
#define CP_WAIT0()   asm volatile("cp.async.wait_group 0;" ::: "memory")

__device__ __forceinline__ void ldsm4(unsigned int* r, unsigned int addr){
    asm volatile("ldmatrix.sync.aligned.m8n8.x4.shared.b16 {%0,%1,%2,%3}, [%4];"
        : "=r"(r[0]),"=r"(r[1]),"=r"(r[2]),"=r"(r[3]) : "r"(addr));
}
__device__ __forceinline__ void mma_bf16(float* d, const unsigned int* a, const unsigned int* b){
    asm volatile("mma.sync.aligned.m16n8k16.row.col.f32.bf16.bf16.f32 "
        "{%0,%1,%2,%3}, {%4,%5,%6,%7}, {%8,%9}, {%0,%1,%2,%3};"
        : "+f"(d[0]),"+f"(d[1]),"+f"(d[2]),"+f"(d[3])
        : "r"(a[0]),"r"(a[1]),"r"(a[2]),"r"(a[3]), "r"(b[0]),"r"(b[1]));
}
__device__ __forceinline__ unsigned int fkey(float f){
    unsigned int u = __float_as_uint(f);
    return (u & 0x80000000u) ? ~u : (u | 0x80000000u);
}
__device__ __forceinline__ float unfkey(unsigned int k){
    unsigned int u = (k & 0x80000000u) ? (k & 0x7FFFFFFFu) : ~k;
    return __uint_as_float(u);
}

// ---------------- prep ----------------
__global__ void prep_emb_kernel(const float* __restrict__ emb){
    int k = blockIdx.x*blockDim.x + threadIdx.x;
    if (k >= Kk) return;
    const float* e = emb + (size_t)k*Cc;
    float acc = 0.0f;
    #pragma unroll 4
    for (int c=0;c<Cc;c++){
        float v = e[c];
        acc = fmaf(v, v, acc);
        g_emb_h[(size_t)k*Cc + c] = __float2bfloat16_rn(v);
    }
    g_esq[k] = acc;
}

// one block per b: frest=f, fhat=0, pool(pn=1) -> rest_h + rsq, per-row state init
__global__ void init_pool_kernel(const float* __restrict__ f){
    __shared__ float s_pool[256];
    int b = blockIdx.x, c = threadIdx.x;
    float acc = 0.0f;
    const float w = (float)(1.0/16.0);
    for (int n=0;n<Nn;n++){
        size_t gi = ((size_t)b*Nn+n)*Cc + c;
        float v = f[gi];
        g_frest[gi] = v;
        g_fhat[gi] = 0.0f;
        acc = fmaf(w, v, acc);
    }
    g_rest_h[(size_t)b*Cc + c] = __float2bfloat16_rn(acc);
    s_pool[c] = acc;
    __syncthreads();
    if (c == 0){
        float r = 0.0f;
        #pragma unroll 8
        for (int i=0;i<Cc;i++) r = fmaf(s_pool[i], s_pool[i], r);
        g_rsq[b] = r;
        g_dmin[b] = 0xFFFFFFFFu;
        g_ccnt[b] = 0;
        if (b == 0) g_loss = 0.0;
    }
}

// ---------------- phase 1: bf16 hi-limb GEMM filter (R12 config, unchanged) ----------------
#define KC 64
#define ROWB 144
#define REG_STRIDE (128*ROWB)
#define STAGE_BYTES (2*REG_STRIDE)
#define NSTAGE 3
#define SMEM_GEMM (NSTAGE*STAGE_BYTES) // 110592

__global__ __launch_bounds__(512,2) void gemm_filter_kernel(){
    extern __shared__ char smem[];
    __shared__ unsigned int sdmin[128];
    __shared__ float sthr[128];
    const int tid = threadIdx.x, lane = tid & 31, wid = tid >> 5;
    const int wm = wid >> 2, wn = wid & 3;
    const int row0 = blockIdx.y * 128, k0 = blockIdx.x * 128;
    const unsigned int sbase = smem_u32(smem);

    if (tid < 128) sdmin[tid] = 0xFFFFFFFFu;

    float acc[2][4][4];
    #pragma unroll
    for (int i=0;i<2;i++)
        #pragma unroll
        for (int j=0;j<4;j++)
            #pragma unroll
            for (int q=0;q<4;q++) acc[i][j][q] = 0.0f;

    const int arow = tid >> 2, apos = (tid & 3) * 2;
    const char* srcA = (const char*)(g_rest_h + (size_t)(row0+arow)*Cc) + apos*16;
    const char* srcB = (const char*)(g_emb_h  + (size_t)(k0 +arow)*Cc) + apos*16;
    const unsigned int adst = arow*ROWB + apos*16;

    #pragma unroll
    for (int c=0;c<2;c++){
        unsigned int st = sbase + c*STAGE_BYTES;
        CP_ASYNC16(st + adst,                   srcA + c*(KC*2));
        CP_ASYNC16(st + adst + 16,              srcA + c*(KC*2) + 16);
        CP_ASYNC16(st + adst + REG_STRIDE,      srcB + c*(KC*2));
        CP_ASYNC16(st + adst + REG_STRIDE + 16, srcB + c*(KC*2) + 16);
        CP_COMMIT();
    }

    const int NCHUNK = Cc / KC;   // 4
    int stage = 0;
    for (int c = 0; c < NCHUNK; c++){
        if (c + 1 < NCHUNK) CP_WAIT1(); else CP_WAIT0();
        __syncthreads();

        if (c + 2 < NCHUNK){
            int ns = stage + 2; if (ns >= NSTAGE) ns -= NSTAGE;
            unsigned int st = sbase + ns*STAGE_BYTES;
            CP_ASYNC16(st + adst,                   srcA + (c+2)*(KC*2));
            CP_ASYNC16(st + adst + 16,              srcA + (c+2)*(KC*2) + 16);
            CP_ASYNC16(st + adst + REG_STRIDE,      srcB + (c+2)*(KC*2));
            CP_ASYNC16(st + adst + REG_STRIDE + 16, srcB + (c+2)*(KC*2) + 16);
            CP_COMMIT();
        }

        unsigned int aA = sbase + stage*STAGE_BYTES;
        unsigned int aB = aA + REG_STRIDE;

        #pragma unroll
        for (int ks=0; ks<4; ks++){
            unsigned int offA = (unsigned int)((wm*32 + (lane&15))*ROWB + (ks*16 + ((lane>>4)<<3))*2);
            unsigned int offB = (unsigned int)((wn*32 + (lane&7) + ((lane>>4)<<3))*ROWB
                                             + (ks*16 + (((lane>>3)&1)<<3))*2);
            unsigned int bh[8];
            ldsm4(bh+0, aB + offB); ldsm4(bh+4, aB + offB + 16*ROWB);
            unsigned int ah[2][4];
            #pragma unroll
            for (int i=0;i<2;i++) ldsm4(ah[i], aA + offA + i*16*ROWB);
            #pragma unroll
            for (int i=0;i<2;i++)
                #pragma unroll
                for (int j=0;j<4;j++)
                    mma_bf16(acc[i][j], ah[i], bh + 2*j);
        }
        stage++; if (stage >= NSTAGE) stage -= NSTAGE;
    }

    const int lr = lane >> 2, lc2 = (lane & 3)*2;
    float rsqv[2][2], esv[4][2];
    #pragma unroll
    for (int i=0;i<2;i++){
        rsqv[i][0] = g_rsq[row0 + wm*32 + i*16 + lr];
        rsqv[i][1] = g_rsq[row0 + wm*32 + i*16 + lr + 8];
    }
    #pragma unroll
    for (int j=0;j<4;j++){
        esv[j][0] = g_esq[k0 + wn*32 + j*8 + lc2];
        esv[j][1] = g_esq[k0 + wn*32 + j*8 + lc2 + 1];
    }
    #pragma unroll
    for (int i=0;i<2;i++){
        unsigned int klo = 0xFFFFFFFFu, khi = 0xFFFFFFFFu;
        #pragma unroll
        for (int j=0;j<4;j++){
            unsigned int k00 = fkey(fmaf(-2.0f, acc[i][j][0], rsqv[i][0] + esv[j][0]));
            unsigned int k01 = fkey(fmaf(-2.0f, acc[i][j][1], rsqv[i][0] + esv[j][1]));
            unsigned int k10 = fkey(fmaf(-2.0f, acc[i][j][2], rsqv[i][1] + esv[j][0]));
            unsigned int k11 = fkey(fmaf(-2.0f, acc[i][j][3], rsqv[i][1] + esv[j][1]));
            klo = min(klo, min(k00,k01));
            khi = min(khi, min(k10,k11));
        }
        #pragma unroll
        for (int off=1; off<=2; off<<=1){
            klo = min(klo, __shfl_xor_sync(0xffffffffu, klo, off));
            khi = min(khi, __shfl_xor_sync(0xffffffffu, khi, off));
        }
        if ((lane & 3) == 0){
            atomicMin(&sdmin[wm*32 + i*16 + lr],     klo);
            atomicMin(&sdmin[wm*32 + i*16 + lr + 8], khi);
        }
    }
    __syncthreads();

    if (tid < 128){
        unsigned int old = atomicMin(&g_dmin[row0 + tid], sdmin[tid]);
        unsigned int m = min(old, sdmin[tid]);
        float dm = unfkey(m);
        float rsq = g_rsq[row0 + tid];
        sthr[tid] = dm + (rsq*4e-7f + 8e-5f);
    }
    __syncthreads();

    #pragma unroll
    for (int i=0;i<2;i++){
        int rlo = wm*32 + i*16 + lr;
        int rhi = rlo + 8;
        float tlo = sthr[rlo], thi = sthr[rhi];
        #pragma unroll
        for (int j=0;j<4;j++){
            int col = k0 + wn*32 + j*8 + lc2;
            float d00 = fmaf(-2.0f, acc[i][j][0], rsqv[i][0] + esv[j][0]);
            float d01 = fmaf(-2.0f, acc[i][j][1], rsqv[i][0] + esv[j][1]);
            float d10 = fmaf(-2.0f, acc[i][j][2], rsqv[i][1] + esv[j][0]);
            float d11 = fmaf(-2.0f, acc[i][j][3], rsqv[i][1] + esv[j][1]);
            if (d00 < tlo){ int s = atomicAdd(&g_ccnt[row0+rlo], 1); if (s < MAXC) g_cand[(size_t)(row0+rlo)*MAXC + s] = col; }
            if (d01 < tlo){ int s = atomicAdd(&g_ccnt[row0+rlo], 1); if (s < MAXC) g_cand[(size_t)(row0+rlo)*MAXC + s] = col+1; }
            if (d10 < thi){ int s = atomicAdd(&g_ccnt[row0+rhi], 1); if (s < MAXC) g_cand[(size_t)(row0+rhi)*MAXC + s] = col; }
            if (d11 < thi){ int s = atomicAdd(&g_ccnt[row0+rhi], 1); if (s < MAXC) g_cand[(size_t)(row0+rhi)*MAXC + s] = col+1; }
        }
    }
}

// ---------------- fused: recompute pool(pn) + rescore + update + pool(pn+1) ----------------
// One block per b (256 threads). smem: s_frest[4096] | s_rest[<=4096] | s_pool[<=4096]
#define SMEM_FUSE (3*4096*4)

__global__ __launch_bounds__(256) void fuse_kernel(const float* __restrict__ f,
                                                  const float* __restrict__ emb,
                                                  int pn, float* __restrict__ out){
    extern __shared__ float sm[];
    float* s_frest = sm;            // 4096
    float* s_rest  = sm + 4096;     // pn*256
    float* s_pool  = sm + 8192;     // (pn+1)*256
    __shared__ unsigned long long s_win[16];
    __shared__ int s_off[17];
    __shared__ double s_red[256];
    const int b = blockIdx.x, tid = threadIdx.x;
    const int base_row = b*pn;

    // load frest (float4 coalesced)
    const float4* gfr4 = (const float4*)(g_frest + (size_t)b*Nn*Cc);
    float4* sfr4 = (float4*)s_frest;
    #pragma unroll
    for (int i=tid; i<1024; i+=256) sfr4[i] = gfr4[i];
    if (tid < pn){
        int cnt = g_ccnt[base_row+tid]; if (cnt > MAXC) cnt = MAXC;
        s_off[tid+1] = cnt;
        s_win[tid] = 0xFFFFFFFFFFFFFFFFull;
    }
    __syncthreads();
    // recompute pooled rows for this stage (bitwise identical to producer's pool)
    for (int i=tid; i<pn*Cc; i+=256){
        int p = i>>8, c = i&255;
        int s = (p*Nn)/pn, e2 = ((p+1)*Nn + pn-1)/pn;
        float w = (float)(1.0/(double)(e2-s));
        float acc = 0.0f;
        for (int n=s;n<e2;n++) acc = fmaf(w, s_frest[n*Cc+c], acc);
        s_rest[i] = acc;
    }
    if (tid == 0){ s_off[0] = 0; for (int p=0;p<pn;p++) s_off[p+1] += s_off[p]; }
    __syncthreads();

    // exact rescore: one thread per candidate, sequential fp32 FMA dot
    int T = s_off[pn];
    for (int g=tid; g<T; g+=256){
        int p = 0;
        while (s_off[p+1] <= g) p++;
        int k = g_cand[(size_t)(base_row+p)*MAXC + (g - s_off[p])];
        const float* e = emb + (size_t)k*Cc;
        const float* r = s_rest + p*Cc;
        float acc = 0.0f;
        #pragma unroll 8
        for (int c=0;c<Cc;c++) acc = fmaf(r[c], __ldg(e+c), acc);
        float d = fmaf(-2.0f, acc, g_rsq[base_row+p] + g_esq[k]);
        unsigned long long key = ((unsigned long long)fkey(d) << 32) | (unsigned int)k;
        atomicMin(&s_win[p], key);
    }
    __syncthreads();

    // update f_hat / f_rest + loss (flattened over float4 elements)
    double lloss = 0.0;
    const float4* f4    = (const float4*)(f + (size_t)b*Nn*Cc);
    float4* fhat4 = (float4*)(g_fhat + (size_t)b*Nn*Cc);
    float4* gfrw4 = (float4*)(g_frest + (size_t)b*Nn*Cc);
    float4* out4  = (float4*)(out + (size_t)b*Nn*Cc);
    for (int i=tid; i<1024; i+=256){
        int n = i>>6;
        int c4 = (i&63)<<2;
        float4 h4;
        if (pn == Nn){
            int k0 = (int)(s_win[n] & 0xFFFFFFFFull);
            h4 = *(const float4*)(emb + (size_t)k0*Cc + c4);
        } else {
            double scale = (double)pn / 16.0;
            double pos = ((double)n + 0.5)*scale - 0.5;
            if (pos < 0.0) pos = 0.0;
            int i0 = (int)floor(pos);
            if (i0 > pn-1) i0 = pn-1;
            double frac = pos - (double)i0;
            int i1 = i0 + 1; if (i1 > pn-1) i1 = pn-1;
            float w0 = (float)(1.0 - frac);
            int k0 = (int)(s_win[i0] & 0xFFFFFFFFull);
            float4 e0 = *(const float4*)(emb + (size_t)k0*Cc + c4);
            if (i1 == i0){
                float w = (float)((double)w0 + frac);
                h4.x = w*e0.x; h4.y = w*e0.y; h4.z = w*e0.z; h4.w = w*e0.w;
            } else {
                float w1 = (float)frac;
                int k1 = (int)(s_win[i1] & 0xFFFFFFFFull);
                float4 e1 = *(const float4*)(emb + (size_t)k1*Cc + c4);
                h4.x = fmaf(w1, e1.x, w0*e0.x);
                h4.y = fmaf(w1, e1.y, w0*e0.y);
                h4.z = fmaf(w1, e1.z, w0*e0.z);
                h4.w = fmaf(w1, e1.w, w0*e0.w);
            }
        }
        float4 fh = fhat4[i];
        fh.x += h4.x; fh.y += h4.y; fh.z += h4.z; fh.w += h4.w;
        if (pn == Nn) out4[i] = fh; else fhat4[i] = fh;
        float4 fr = sfr4[i];
        fr.x -= h4.x; fr.y -= h4.y; fr.z -= h4.z; fr.w -= h4.w;
        sfr4[i] = fr;
        if (pn < Nn) gfrw4[i] = fr;
        float4 fv = f4[i];
        float tx = fh.x - fv.x, ty = fh.y - fv.y, tz = fh.z - fv.z, tw = fh.w - fv.w;
        lloss += (double)tx*tx + (double)ty*ty + (double)tz*tz + (double)tw*tw;
    }
    s_red[tid] = lloss;
    __syncthreads();
    for (int s=128;s>0;s>>=1){
        if (tid < s) s_red[tid] += s_red[tid+s];
        __syncthreads();
    }
    if (tid == 0) atomicAdd(&g_loss, s_red[0]);

    // pool for next stage -> rest_h + rsq + state init
    if (pn < Nn){
        int np = pn + 1;
        for (int i=tid; i<np*Cc; i+=256){
            int p = i>>8, c = i&255;
            int s = (p*Nn)/np, e2 = ((p+1)*Nn + np-1)/np;
            float w = (float)(1.0/(double)(e2-s));
            float acc = 0.0f;
            for (int n=s;n<e2;n++) acc = fmaf(w, s_frest[n*Cc+c], acc);
            s_pool[i] = acc;
            g_rest_h[((size_t)(b*np + p))*Cc + c] = __float2bfloat16_rn(acc);
        }
        __syncthreads();
        if (tid < np){
            const float* pr = s_pool + tid*Cc;
            float r = 0.0f;
            #pragma unroll 8
            for (int i2=0;i2<Cc;i2++) r = fmaf(pr[i2], pr[i2], r);
            int row = b*np + tid;
            g_rsq[row] = r;
            g_dmin[row] = 0xFFFFFFFFu;
            g_ccnt[row] = 0;
        }
    }
}

__global__ void finalize_loss_kernel(float* __restrict__ out){
    double S = g_loss / (double)(Bb*Nn*Cc);
    out[Bb*Nn*Cc]     = (float)(0.25 * S / 16.0);   // commit
    out[Bb*Nn*Cc + 1] = (float)(S / 16.0);          // qlat
}

extern "C" void kernel_launch(void* const* d_in, const int* in_sizes, int n_in,
                              void* d_out, int out_size){
    const float* f   = (const float*)d_in[0];
    const float* emb = (const float*)d_in[1];
    float* out = (float*)d_out;

    cudaFuncSetAttribute(gemm_filter_kernel, cudaFuncAttributeMaxDynamicSharedMemorySize, SMEM_GEMM);
    cudaFuncSetAttribute(fuse_kernel, cudaFuncAttributeMaxDynamicSharedMemorySize, SMEM_FUSE);

    prep_emb_kernel<<<(Kk + 255)/256, 256>>>(emb);
    init_pool_kernel<<<Bb, 256>>>(f);

    for (int pn=1; pn<=Nn; pn++){
        int M = Bb*pn;
        dim3 grid(Kk/128, M/128);
        gemm_filter_kernel<<<grid, 512, SMEM_GEMM>>>();
        fuse_kernel<<<Bb, 256, SMEM_FUSE>>>(f, emb, pn, out);
    }
    finalize_loss_kernel<<<1, 1>>>(out);
}

// round 17
// speedup vs baseline: 1.9152x; 1.0611x over previous
#include <cuda_runtime.h>
#include <cuda_bf16.h>
#include <stdint.h>
#include <math.h>

#define Bb 512
#define Nn 16
#define Cc 256
#define Kk 8192
#define MAXC 512

// ---------------- device globals (no allocations allowed) ----------------
__device__ float g_frest[Bb*Nn*Cc];
__device__ __nv_bfloat16 g_rest_h[Bb*Nn*Cc];
__device__ __nv_bfloat16 g_emb_h[Kk*Cc];
__device__ float g_rsq  [Bb*Nn];
__device__ float g_esq  [Kk];
__device__ unsigned int g_dmin[Bb*Nn];
__device__ int g_ccnt[Bb*Nn];
__device__ int g_cand[Bb*Nn*MAXC];
__device__ double g_loss;

// ---------------- helpers ----------------
__device__ __forceinline__ unsigned int smem_u32(const void* p){
    unsigned int a;
    asm("{ .reg .u64 t; cvta.to.shared.u64 t, %1; cvt.u32.u64 %0, t; }" : "=r"(a) : "l"(p));
    return a;
}
#define CP_ASYNC16(dst,src) asm volatile("cp.async.cg.shared.global [%0], [%1], 16;" :: "r"(dst), "l"(src))
#define CP_COMMIT()  asm volatile("cp.async.commit_group;" ::: "memory")
#define CP_WAIT1()   asm volatile("cp.async.wait_group 1;" ::: "memory")
#define CP_WAIT0()   asm volatile("cp.async.wait_group 0;" ::: "memory")

__device__ __forceinline__ void ldsm4(unsigned int* r, unsigned int addr){
    asm volatile("ldmatrix.sync.aligned.m8n8.x4.shared.b16 {%0,%1,%2,%3}, [%4];"
        : "=r"(r[0]),"=r"(r[1]),"=r"(r[2]),"=r"(r[3]) : "r"(addr));
}
__device__ __forceinline__ void mma_bf16(float* d, const unsigned int* a, const unsigned int* b){
    asm volatile("mma.sync.aligned.m16n8k16.row.col.f32.bf16.bf16.f32 "
        "{%0,%1,%2,%3}, {%4,%5,%6,%7}, {%8,%9}, {%0,%1,%2,%3};"
        : "+f"(d[0]),"+f"(d[1]),"+f"(d[2]),"+f"(d[3])
        : "r"(a[0]),"r"(a[1]),"r"(a[2]),"r"(a[3]), "r"(b[0]),"r"(b[1]));
}
__device__ __forceinline__ unsigned int fkey(float f){
    unsigned int u = __float_as_uint(f);
    return (u & 0x80000000u) ? ~u : (u | 0x80000000u);
}
__device__ __forceinline__ float unfkey(unsigned int k){
    unsigned int u = (k & 0x80000000u) ? (k & 0x7FFFFFFFu) : ~k;
    return __uint_as_float(u);
}

// ---------------- prep ----------------
__global__ void prep_emb_kernel(const float* __restrict__ emb){
    int k = blockIdx.x*blockDim.x + threadIdx.x;
    if (k >= Kk) return;
    const float* e = emb + (size_t)k*Cc;
    float acc = 0.0f;
    #pragma unroll 4
    for (int c=0;c<Cc;c++){
        float v = e[c];
        acc = fmaf(v, v, acc);
        g_emb_h[(size_t)k*Cc + c] = __float2bfloat16_rn(v);
    }
    g_esq[k] = acc;
}

// one block per b: frest=f, pool(pn=1) -> rest_h + rsq, per-row state init
__global__ void init_pool_kernel(const float* __restrict__ f){
    __shared__ float s_pool[256];
    int b = blockIdx.x, c = threadIdx.x;
    float acc = 0.0f;
    const float w = (float)(1.0/16.0);
    for (int n=0;n<Nn;n++){
        size_t gi = ((size_t)b*Nn+n)*Cc + c;
        float v = f[gi];
        g_frest[gi] = v;
        acc = fmaf(w, v, acc);
    }
    g_rest_h[(size_t)b*Cc + c] = __float2bfloat16_rn(acc);
    s_pool[c] = acc;
    __syncthreads();
    if (c == 0){
        float r = 0.0f;
        #pragma unroll 8
        for (int i=0;i<Cc;i++) r = fmaf(s_pool[i], s_pool[i], r);
        g_rsq[b] = r;
        g_dmin[b] = 0xFFFFFFFFu;
        g_ccnt[b] = 0;
        if (b == 0) g_loss = 0.0;
    }
}

// ---------------- phase 1: bf16 hi-limb GEMM filter (unchanged) ----------------
#define KC 64
#define ROWB 144
#define REG_STRIDE (128*ROWB)
#define STAGE_BYTES (2*REG_STRIDE)
#define NSTAGE 3
#define SMEM_GEMM (NSTAGE*STAGE_BYTES) // 110592

__global__ __launch_bounds__(512,2) void gemm_filter_kernel(){
    extern __shared__ char smem[];
    __shared__ unsigned int sdmin[128];
    __shared__ float sthr[128];
    const int tid = threadIdx.x, lane = tid & 31, wid = tid >> 5;
    const int wm = wid >> 2, wn = wid & 3;
    const int row0 = blockIdx.y * 128, k0 = blockIdx.x * 128;
    const unsigned int sbase = smem_u32(smem);

    if (tid < 128) sdmin[tid] = 0xFFFFFFFFu;

    float acc[2][4][4];
    #pragma unroll
    for (int i=0;i<2;i++)
        #pragma unroll
        for (int j=0;j<4;j++)
            #pragma unroll
            for (int q=0;q<4;q++) acc[i][j][q] = 0.0f;

    const int arow = tid >> 2, apos = (tid & 3) * 2;
    const char* srcA = (const char*)(g_rest_h + (size_t)(row0+arow)*Cc) + apos*16;
    const char* srcB = (const char*)(g_emb_h  + (size_t)(k0 +arow)*Cc) + apos*16;
    const unsigned int adst = arow*ROWB + apos*16;

    #pragma unroll
    for (int c=0;c<2;c++){
        unsigned int st = sbase + c*STAGE_BYTES;
        CP_ASYNC16(st + adst,                   srcA + c*(KC*2));
        CP_ASYNC16(st + adst + 16,              srcA + c*(KC*2) + 16);
        CP_ASYNC16(st + adst + REG_STRIDE,      srcB + c*(KC*2));
        CP_ASYNC16(st + adst + REG_STRIDE + 16, srcB + c*(KC*2) + 16);
        CP_COMMIT();
    }

    const int NCHUNK = Cc / KC;   // 4
    int stage = 0;
    for (int c = 0; c < NCHUNK; c++){
        if (c + 1 < NCHUNK) CP_WAIT1(); else CP_WAIT0();
        __syncthreads();

        if (c + 2 < NCHUNK){
            int ns = stage + 2; if (ns >= NSTAGE) ns -= NSTAGE;
            unsigned int st = sbase + ns*STAGE_BYTES;
            CP_ASYNC16(st + adst,                   srcA + (c+2)*(KC*2));
            CP_ASYNC16(st + adst + 16,              srcA + (c+2)*(KC*2) + 16);
            CP_ASYNC16(st + adst + REG_STRIDE,      srcB + (c+2)*(KC*2));
            CP_ASYNC16(st + adst + REG_STRIDE + 16, srcB + (c+2)*(KC*2) + 16);
            CP_COMMIT();
        }

        unsigned int aA = sbase + stage*STAGE_BYTES;
        unsigned int aB = aA + REG_STRIDE;

        #pragma unroll
        for (int ks=0; ks<4; ks++){
            unsigned int offA = (unsigned int)((wm*32 + (lane&15))*ROWB + (ks*16 + ((lane>>4)<<3))*2);
            unsigned int offB = (unsigned int)((wn*32 + (lane&7) + ((lane>>4)<<3))*ROWB
                                             + (ks*16 + (((lane>>3)&1)<<3))*2);
            unsigned int bh[8];
            ldsm4(bh+0, aB + offB); ldsm4(bh+4, aB + offB + 16*ROWB);
            unsigned int ah[2][4];
            #pragma unroll
            for (int i=0;i<2;i++) ldsm4(ah[i], aA + offA + i*16*ROWB);
            #pragma unroll
            for (int i=0;i<2;i++)
                #pragma unroll
                for (int j=0;j<4;j++)
                    mma_bf16(acc[i][j], ah[i], bh + 2*j);
        }
        stage++; if (stage >= NSTAGE) stage -= NSTAGE;
    }

    const int lr = lane >> 2, lc2 = (lane & 3)*2;
    float rsqv[2][2], esv[4][2];
    #pragma unroll
    for (int i=0;i<2;i++){
        rsqv[i][0] = g_rsq[row0 + wm*32 + i*16 + lr];
        rsqv[i][1] = g_rsq[row0 + wm*32 + i*16 + lr + 8];
    }
    #pragma unroll
    for (int j=0;j<4;j++){
        esv[j][0] = g_esq[k0 + wn*32 + j*8 + lc2];
        esv[j][1] = g_esq[k0 + wn*32 + j*8 + lc2 + 1];
    }
    #pragma unroll
    for (int i=0;i<2;i++){
        unsigned int klo = 0xFFFFFFFFu, khi = 0xFFFFFFFFu;
        #pragma unroll
        for (int j=0;j<4;j++){
            unsigned int k00 = fkey(fmaf(-2.0f, acc[i][j][0], rsqv[i][0] + esv[j][0]));
            unsigned int k01 = fkey(fmaf(-2.0f, acc[i][j][1], rsqv[i][0] + esv[j][1]));
            unsigned int k10 = fkey(fmaf(-2.0f, acc[i][j][2], rsqv[i][1] + esv[j][0]));
            unsigned int k11 = fkey(fmaf(-2.0f, acc[i][j][3], rsqv[i][1] + esv[j][1]));
            klo = min(klo, min(k00,k01));
            khi = min(khi, min(k10,k11));
        }
        #pragma unroll
        for (int off=1; off<=2; off<<=1){
            klo = min(klo, __shfl_xor_sync(0xffffffffu, klo, off));
            khi = min(khi, __shfl_xor_sync(0xffffffffu, khi, off));
        }
        if ((lane & 3) == 0){
            atomicMin(&sdmin[wm*32 + i*16 + lr],     klo);
            atomicMin(&sdmin[wm*32 + i*16 + lr + 8], khi);
        }
    }
    __syncthreads();

    if (tid < 128){
        unsigned int old = atomicMin(&g_dmin[row0 + tid], sdmin[tid]);
        unsigned int m = min(old, sdmin[tid]);
        float dm = unfkey(m);
        float rsq = g_rsq[row0 + tid];
        sthr[tid] = dm + (rsq*4e-7f + 8e-5f);
    }
    __syncthreads();

    #pragma unroll
    for (int i=0;i<2;i++){
        int rlo = wm*32 + i*16 + lr;
        int rhi = rlo + 8;
        float tlo = sthr[rlo], thi = sthr[rhi];
        #pragma unroll
        for (int j=0;j<4;j++){
            int col = k0 + wn*32 + j*8 + lc2;
            float d00 = fmaf(-2.0f, acc[i][j][0], rsqv[i][0] + esv[j][0]);
            float d01 = fmaf(-2.0f, acc[i][j][1], rsqv[i][0] + esv[j][1]);
            float d10 = fmaf(-2.0f, acc[i][j][2], rsqv[i][1] + esv[j][0]);
            float d11 = fmaf(-2.0f, acc[i][j][3], rsqv[i][1] + esv[j][1]);
            if (d00 < tlo){ int s = atomicAdd(&g_ccnt[row0+rlo], 1); if (s < MAXC) g_cand[(size_t)(row0+rlo)*MAXC + s] = col; }
            if (d01 < tlo){ int s = atomicAdd(&g_ccnt[row0+rlo], 1); if (s < MAXC) g_cand[(size_t)(row0+rlo)*MAXC + s] = col+1; }
            if (d10 < thi){ int s = atomicAdd(&g_ccnt[row0+rhi], 1); if (s < MAXC) g_cand[(size_t)(row0+rhi)*MAXC + s] = col; }
            if (d11 < thi){ int s = atomicAdd(&g_ccnt[row0+rhi], 1); if (s < MAXC) g_cand[(size_t)(row0+rhi)*MAXC + s] = col+1; }
        }
    }
}

// ---------------- fused: recompute pool(pn) + rescore + update + pool(pn+1) ----------------
// One block per b (512 threads). smem: s_frest[4096] | s_rest[4096] (s_pool overlays s_rest)
#define SMEM_FUSE (2*4096*4)

__global__ __launch_bounds__(512) void fuse_kernel(const float* __restrict__ f,
                                                  const float* __restrict__ emb,
                                                  int pn, float* __restrict__ out){
    extern __shared__ float sm[];
    float* s_frest = sm;            // 4096
    float* s_rest  = sm + 4096;     // pn*256 (reused as s_pool after rescore)
    __shared__ unsigned long long s_win[16];
    __shared__ int s_off[17];
    __shared__ double s_red[512];
    const int b = blockIdx.x, tid = threadIdx.x;
    const int base_row = b*pn;

    // load frest (float4 coalesced)
    const float4* gfr4 = (const float4*)(g_frest + (size_t)b*Nn*Cc);
    float4* sfr4 = (float4*)s_frest;
    #pragma unroll
    for (int i=tid; i<1024; i+=512) sfr4[i] = gfr4[i];
    if (tid < pn){
        int cnt = g_ccnt[base_row+tid]; if (cnt > MAXC) cnt = MAXC;
        s_off[tid+1] = cnt;
        s_win[tid] = 0xFFFFFFFFFFFFFFFFull;
    }
    __syncthreads();
    // recompute pooled rows for this stage (bitwise identical to producer's pool)
    for (int i=tid; i<pn*Cc; i+=512){
        int p = i>>8, c = i&255;
        int s = (p*Nn)/pn, e2 = ((p+1)*Nn + pn-1)/pn;
        float w = (float)(1.0/(double)(e2-s));
        float acc = 0.0f;
        for (int n=s;n<e2;n++) acc = fmaf(w, s_frest[n*Cc+c], acc);
        s_rest[i] = acc;
    }
    if (tid == 0){ s_off[0] = 0; for (int p=0;p<pn;p++) s_off[p+1] += s_off[p]; }
    __syncthreads();

    // exact rescore: one thread per candidate, sequential fp32 FMA dot
    int T = s_off[pn];
    for (int g=tid; g<T; g+=512){
        int p = 0;
        while (s_off[p+1] <= g) p++;
        int k = g_cand[(size_t)(base_row+p)*MAXC + (g - s_off[p])];
        const float* e = emb + (size_t)k*Cc;
        const float* r = s_rest + p*Cc;
        float acc = 0.0f;
        #pragma unroll 8
        for (int c=0;c<Cc;c++) acc = fmaf(r[c], __ldg(e+c), acc);
        float d = fmaf(-2.0f, acc, g_rsq[base_row+p] + g_esq[k]);
        unsigned long long key = ((unsigned long long)fkey(d) << 32) | (unsigned int)k;
        atomicMin(&s_win[p], key);
    }
    __syncthreads();

    // update f_rest + loss (loss t = fh - f = -fr up to the same rounding chain)
    double lloss = 0.0;
    float4* gfrw4 = (float4*)(g_frest + (size_t)b*Nn*Cc);
    const float4* f4 = (const float4*)(f + (size_t)b*Nn*Cc);
    float4* out4 = (float4*)(out + (size_t)b*Nn*Cc);
    for (int i=tid; i<1024; i+=512){
        int n = i>>6;
        int c4 = (i&63)<<2;
        float4 h4;
        if (pn == Nn){
            int k0 = (int)(s_win[n] & 0xFFFFFFFFull);
            h4 = *(const float4*)(emb + (size_t)k0*Cc + c4);
        } else {
            double scale = (double)pn / 16.0;
            double pos = ((double)n + 0.5)*scale - 0.5;
            if (pos < 0.0) pos = 0.0;
            int i0 = (int)floor(pos);
            if (i0 > pn-1) i0 = pn-1;
            double frac = pos - (double)i0;
            int i1 = i0 + 1; if (i1 > pn-1) i1 = pn-1;
            float w0 = (float)(1.0 - frac);
            int k0 = (int)(s_win[i0] & 0xFFFFFFFFull);
            float4 e0 = *(const float4*)(emb + (size_t)k0*Cc + c4);
            if (i1 == i0){
                float w = (float)((double)w0 + frac);
                h4.x = w*e0.x; h4.y = w*e0.y; h4.z = w*e0.z; h4.w = w*e0.w;
            } else {
                float w1 = (float)frac;
                int k1 = (int)(s_win[i1] & 0xFFFFFFFFull);
                float4 e1 = *(const float4*)(emb + (size_t)k1*Cc + c4);
                h4.x = fmaf(w1, e1.x, w0*e0.x);
                h4.y = fmaf(w1, e1.y, w0*e0.y);
                h4.z = fmaf(w1, e1.z, w0*e0.z);
                h4.w = fmaf(w1, e1.w, w0*e0.w);
            }
        }
        float4 fr = sfr4[i];
        fr.x -= h4.x; fr.y -= h4.y; fr.z -= h4.z; fr.w -= h4.w;
        sfr4[i] = fr;
        if (pn < Nn){
            gfrw4[i] = fr;
        } else {
            float4 fv = f4[i];
            float4 ov;
            ov.x = fv.x - fr.x; ov.y = fv.y - fr.y; ov.z = fv.z - fr.z; ov.w = fv.w - fr.w;
            out4[i] = ov;
        }
        lloss += (double)fr.x*fr.x + (double)fr.y*fr.y + (double)fr.z*fr.z + (double)fr.w*fr.w;
    }
    s_red[tid] = lloss;
    __syncthreads();
    for (int s=256;s>0;s>>=1){
        if (tid < s) s_red[tid] += s_red[tid+s];
        __syncthreads();
    }
    if (tid == 0) atomicAdd(&g_loss, s_red[0]);

    // pool for next stage (s_rest region reused) -> rest_h + rsq + state init
    if (pn < Nn){
        int np = pn + 1;
        for (int i=tid; i<np*Cc; i+=512){
            int p = i>>8, c = i&255;
            int s = (p*Nn)/np, e2 = ((p+1)*Nn + np-1)/np;
            float w = (float)(1.0/(double)(e2-s));
            float acc = 0.0f;
            for (int n=s;n<e2;n++) acc = fmaf(w, s_frest[n*Cc+c], acc);
            s_rest[i] = acc;
            g_rest_h[((size_t)(b*np + p))*Cc + c] = __float2bfloat16_rn(acc);
        }
        __syncthreads();
        if (tid < np){
            const float* pr = s_rest + tid*Cc;
            float r = 0.0f;
            #pragma unroll 8
            for (int i2=0;i2<Cc;i2++) r = fmaf(pr[i2], pr[i2], r);
            int row = b*np + tid;
            g_rsq[row] = r;
            g_dmin[row] = 0xFFFFFFFFu;
            g_ccnt[row] = 0;
        }
    }
}

__global__ void finalize_loss_kernel(float* __restrict__ out){
    double S = g_loss / (double)(Bb*Nn*Cc);
    out[Bb*Nn*Cc]     = (float)(0.25 * S / 16.0);   // commit
    out[Bb*Nn*Cc + 1] = (float)(S / 16.0);          // qlat
}

extern "C" void kernel_launch(void* const* d_in, const int* in_sizes, int n_in,
                              void* d_out, int out_size){
    const float* f   = (const float*)d_in[0];
    const float* emb = (const float*)d_in[1];
    float* out = (float*)d_out;

    cudaFuncSetAttribute(gemm_filter_kernel, cudaFuncAttributeMaxDynamicSharedMemorySize, SMEM_GEMM);
    cudaFuncSetAttribute(fuse_kernel, cudaFuncAttributeMaxDynamicSharedMemorySize, SMEM_FUSE);

    prep_emb_kernel<<<(Kk + 255)/256, 256>>>(emb);
    init_pool_kernel<<<Bb, 256>>>(f);

    for (int pn=1; pn<=Nn; pn++){
        int M = Bb*pn;
        dim3 grid(Kk/128, M/128);
        gemm_filter_kernel<<<grid, 512, SMEM_GEMM>>>();
        fuse_kernel<<<Bb, 512, SMEM_FUSE>>>(f, emb, pn, out);
    }
    finalize_loss_kernel<<<1, 1>>>(out);
}